// round 17
// baseline (speedup 1.0000x reference)
#include <cuda_runtime.h>
#include <cstdint>

// ---------------------------------------------------------------------------
// HybridSigLSTM: rolling signature + 2-layer LSTM(H=50) + MLP head + pd clip
// B=4096, S=256, DIN=4, WIN=5, D_AUG=5, SIG=30, COMB=35, GATES=4*50=200
// ---------------------------------------------------------------------------

#define B_TOT 4096
#define S_LEN 256
#define GATES 200
#define BT    28      // batch elements per CTA in recurrent kernel
#define NT    384     // threads in recurrent kernel (12 warps)

typedef unsigned long long u64;

// scratch (device global: allocation-free rule)
__device__ float g_pre0[(size_t)B_TOT * S_LEN * 200];  // [t][b][o]

// ---------------- helpers ----------------
__device__ __forceinline__ u64 ffma2(u64 a, u64 b, u64 c) {
    u64 d;
    asm("fma.rn.f32x2 %0, %1, %2, %3;" : "=l"(d) : "l"(a), "l"(b), "l"(c));
    return d;
}
__device__ __forceinline__ u64 pack2(float a, float b) {
    u64 r;
    asm("mov.b64 %0, {%1, %2};" : "=l"(r) : "f"(a), "f"(b));
    return r;
}
__device__ __forceinline__ float2 unpack2(u64 v) {
    float2 f;
    asm("mov.b64 {%0, %1}, %2;" : "=f"(f.x), "=f"(f.y) : "l"(v));
    return f;
}
__device__ __forceinline__ float ex2f(float x) {
    float y; asm("ex2.approx.f32 %0, %1;" : "=f"(y) : "f"(x)); return y;
}
__device__ __forceinline__ float rcpf(float x) {
    float y; asm("rcp.approx.f32 %0, %1;" : "=f"(y) : "f"(x)); return y;
}
__device__ __forceinline__ float sigf(float x) {
    return rcpf(1.0f + ex2f(-1.4426950408889634f * x));
}
__device__ __forceinline__ float tanha(float x) {
    return 2.0f * rcpf(1.0f + ex2f(-2.8853900817779268f * x)) - 1.0f;
}
__device__ __forceinline__ void cpasync16(uint32_t saddr, const void* gptr) {
    asm volatile("cp.async.cg.shared.global [%0], [%1], 16;" :: "r"(saddr), "l"(gptr));
}
__device__ __forceinline__ void cpcommit() {
    asm volatile("cp.async.commit_group;" ::: "memory");
}
__device__ __forceinline__ void cpwait0() {
    asm volatile("cp.async.wait_group 0;" ::: "memory");
}
__device__ __forceinline__ void barS(int id, int cnt) {
    asm volatile("bar.sync %0, %1;" :: "r"(id), "r"(cnt) : "memory");
}
__device__ __forceinline__ void barA(int id, int cnt) {
    asm volatile("bar.arrive %0, %1;" :: "r"(id), "r"(cnt) : "memory");
}

// ---------------------------------------------------------------------------
// K1: fused signature + input projection. One CTA = full sequence of one b.
// ---------------------------------------------------------------------------
__global__ __launch_bounds__(256) void pre0f_kernel(const float* __restrict__ features,
                                                    const float* __restrict__ w_ih0,
                                                    const float* __restrict__ b_ih0,
                                                    const float* __restrict__ b_hh0) {
    __shared__ __align__(16) float4 sf[260];         // raw feature window (t-4..t+255)
    __shared__ __align__(16) float xs[256][36];
    const int tid = threadIdx.x;
    const int b   = blockIdx.x;

    for (int i = tid; i < 260; i += 256) {
        int gi = i - 4; if (gi < 0) gi = 0;
        sf[i] = __ldg((const float4*)features + (size_t)b * S_LEN + gi);
    }

    u64 wp[17];
    float bias = 0.0f;
    if (tid < GATES) {
        const float* wr = w_ih0 + tid * 35;
#pragma unroll
        for (int j = 0; j < 17; j++) wp[j] = pack2(wr[2 * j], wr[2 * j + 1]);
        bias = b_ih0[tid] + b_hh0[tid];
    }
    __syncthreads();

    {   // every thread computes sig features for row t = tid
        const int t = tid;
        float a[5][5];
#pragma unroll
        for (int k = 0; k < 5; k++) {
            int gi = t + k - 4;
            int idx = gi < 0 ? 0 : gi;
            float4 fv = sf[t + k];
            a[k][0] = (float)idx * (1.0f / 255.0f);
            a[k][1] = fv.x; a[k][2] = fv.y; a[k][3] = fv.z; a[k][4] = fv.w;
        }
        float* x = xs[t];
        x[0] = a[4][1]; x[1] = a[4][2]; x[2] = a[4][3]; x[3] = a[4][4];
#pragma unroll
        for (int i = 0; i < 5; i++) x[4 + i] = a[4][i] - a[0][i];
#pragma unroll
        for (int i = 0; i < 5; i++) {
#pragma unroll
            for (int j = 0; j < 5; j++) {
                float s = 0.0f;
#pragma unroll
                for (int k = 0; k < 4; k++) s += (a[k + 1][i] - a[k][i]) * a[k][j];
                x[9 + i * 5 + j] = s;
            }
        }
        x[34] = 0.0f; x[35] = 0.0f;
    }
    __syncthreads();

    if (tid < GATES) {
        for (int r = 0; r < 256; r += 2) {
            const ulonglong2* xA = (const ulonglong2*)&xs[r][0];
            const ulonglong2* xB = (const ulonglong2*)&xs[r + 1][0];
            u64 aA = 0ull, aB = 0ull;
#pragma unroll
            for (int q = 0; q < 8; q++) {
                ulonglong2 vA = xA[q], vB = xB[q];
                aA = ffma2(wp[2 * q],     vA.x, aA);
                aB = ffma2(wp[2 * q],     vB.x, aB);
                aA = ffma2(wp[2 * q + 1], vA.y, aA);
                aB = ffma2(wp[2 * q + 1], vB.y, aB);
            }
            u64 tA = ((const u64*)&xs[r][0])[16];
            u64 tB = ((const u64*)&xs[r + 1][0])[16];
            aA = ffma2(wp[16], tA, aA);
            aB = ffma2(wp[16], tB, aB);
            float2 fA = unpack2(aA), fB = unpack2(aB);
            size_t ia = ((size_t)r       * B_TOT + b) * 200 + tid;   // [t][b][o]
            size_t ib = ((size_t)(r + 1) * B_TOT + b) * 200 + tid;
            g_pre0[ia] = fA.x + fA.y + bias;
            g_pre0[ib] = fB.x + fB.y + bias;
        }
    }
}

// ---------------------------------------------------------------------------
// K2: warp-specialized recurrent kernel with named-barrier pipelining.
// CRIT = warps 0-5 (192 thr): act0 -> z1p -> act1 -> head (critical chain)
//   - Wih1 rows 0-191 on threads 0-191; rows 192-199 on warp5 lanes 24-31.
//   - head on warps 0-4, w1 columns in registers (wrB of lane<25).
//   - warp5 lanes 0-15 compute z0s/p2 extra rows 192-199 during head phase.
// BG   = warps 6-11 (192 thr): p2(t)=Whh1*h1(t-1) || act0; z0s(t+1)=Whh0*h0
//   || act1+head; cp.async prefetch. 2 weight rows per thread max.
// Named barriers: 1=p2ready 2=h1ready 3=h0ready 4=z0ready (384), 5=CRIT(192).
// ---------------------------------------------------------------------------
// dynamic SMEM layout (floats):
//   B0 @0 (5600) | B1 @5600 | p2s @11200 | z0s @16800 | h0s @22400 (1456)
//   h1s @23856 (1456) | pd_s @25312 (28) | wpd_s @25340 (200)
//   b2 @25540
#define SM_FLOATS 25544

// 1-row x 2-batch matvec over SRC (52-float rows), dst stride 200
#define MV1(SRC, W, DST, BIAS)                                                 \
    for (int b = 0; b < bt; b += 2) {                                          \
        const ulonglong2* hA = (const ulonglong2*)((SRC) + b * 52);            \
        const ulonglong2* hB = (const ulonglong2*)((SRC) + (b + 1) * 52);      \
        u64 a0 = 0ull, a1 = 0ull;                                              \
        _Pragma("unroll")                                                      \
        for (int j = 0; j < 12; j++) {                                         \
            ulonglong2 vA = hA[j], vB = hB[j];                                 \
            a0 = ffma2((W)[2 * j],     vA.x, a0);                              \
            a1 = ffma2((W)[2 * j],     vB.x, a1);                              \
            a0 = ffma2((W)[2 * j + 1], vA.y, a0);                              \
            a1 = ffma2((W)[2 * j + 1], vB.y, a1);                              \
        }                                                                      \
        u64 tA = ((const u64*)((SRC) + b * 52))[24];                           \
        u64 tB = ((const u64*)((SRC) + (b + 1) * 52))[24];                     \
        a0 = ffma2((W)[24], tA, a0);                                           \
        a1 = ffma2((W)[24], tB, a1);                                           \
        float2 f0 = unpack2(a0), f1 = unpack2(a1);                             \
        (DST)[b * 200]       = (BIAS) + f0.x + f0.y;                           \
        (DST)[(b + 1) * 200] = (BIAS) + f1.x + f1.y;                           \
    }

__global__ __launch_bounds__(NT, 1) void rec_kernel(
    const float* __restrict__ w_ih0, const float* __restrict__ w_hh0,
    const float* __restrict__ w_ih1, const float* __restrict__ w_hh1,
    const float* __restrict__ b_ih1, const float* __restrict__ b_hh1,
    const float* __restrict__ w1,    const float* __restrict__ b1,
    const float* __restrict__ w2,    const float* __restrict__ b2,
    float* __restrict__ out)
{
    extern __shared__ __align__(16) float sm[];
    float* Bf0  = sm;
    float* Bf1  = sm + 5600;
    float* p2s  = sm + 11200;
    float* z0s  = sm + 16800;
    float* h0s  = sm + 22400;
    float* h1s  = sm + 23856;
    float* pd_s = sm + 25312;
    float* wpd_s= sm + 25340;
    float* b2sp = sm + 25540;

    const int tid  = threadIdx.x;
    const int wid  = tid >> 5;
    const int lane = tid & 31;
    const int b0   = blockIdx.x * BT;
    int bt = B_TOT - b0; if (bt > BT) bt = BT;     // 28 or 8 (even)
    const bool isCrit = (tid < 192);

    // ---- weights ----
    u64 wrA[25], wrB[25];
    float bias0 = 0.0f, bias1e = 0.0f, b1v = 0.0f, w2v = 0.0f;
    if (isCrit) {
        const float* ra = w_ih1 + tid * 50;            // Wih1 row tid
#pragma unroll
        for (int q = 0; q < 25; q++) wrA[q] = pack2(ra[2 * q], ra[2 * q + 1]);
        bias0 = b_ih1[tid] + b_hh1[tid];
        if (wid == 5) {
            // warp5 extras: rows 192-199 of each matrix
            const float* rb = nullptr;
            if (lane < 8)        rb = w_hh0 + (192 + lane) * 50;       // z0s-extra
            else if (lane < 16)  rb = w_hh1 + (184 + lane) * 50;       // p2-extra
            else if (lane >= 24) {
                rb = w_ih1 + (168 + lane) * 50;                        // z1p-extra
                bias1e = b_ih1[168 + lane] + b_hh1[168 + lane];
            }
            if (rb) {
#pragma unroll
                for (int q = 0; q < 25; q++) wrB[q] = pack2(rb[2 * q], rb[2 * q + 1]);
            }
        } else if (lane < 25) {
            const float* wc = w1 + lane * 50;          // w1 column for head
#pragma unroll
            for (int q = 0; q < 25; q++) wrB[q] = pack2(wc[2 * q], wc[2 * q + 1]);
            b1v = b1[lane]; w2v = w2[lane];
        }
    } else {
        const int g = tid - 192;
        const float* r0 = w_hh0 + g * 50;              // z0s row g
        const float* r1 = w_hh1 + g * 50;              // p2 row g
#pragma unroll
        for (int q = 0; q < 25; q++) {
            wrA[q] = pack2(r0[2 * q], r0[2 * q + 1]);
            wrB[q] = pack2(r1[2 * q], r1[2 * q + 1]);
        }
    }

    // ---- init shared state ----
    for (int i = tid; i < BT * 52; i += NT) { h0s[i] = 0.0f; h1s[i] = 0.0f; }
    for (int i = tid; i < BT * 200; i += NT) { z0s[i] = 0.0f; p2s[i] = 0.0f; }
    for (int i = tid; i < 200; i += NT) wpd_s[i] = w_ih0[i * 35 + 34];
    if (tid < BT) pd_s[tid] = 0.0f;
    if (tid == 0) b2sp[0] = b2[0];
    float c0r[8], c1r[8];
#pragma unroll
    for (int n = 0; n < 8; n++) { c0r[n] = 0.0f; c1r[n] = 0.0f; }

    const int nact2 = bt * 25;   // (u,u+1)-pair items per act phase
    const int nz4   = bt * 50;   // float4 count of a pre0 tile
    const uint32_t smB0 = (uint32_t)__cvta_generic_to_shared(Bf0);
    const uint32_t smB1 = (uint32_t)__cvta_generic_to_shared(Bf1);

    // prologue: fetch P(0) -> B0 and P(1) -> B1
    {
        const float4* p0 = (const float4*)(g_pre0 + (size_t)b0 * 200);
        const float4* p1 = (const float4*)(g_pre0 + ((size_t)1 * B_TOT + b0) * 200);
        for (int idx = tid; idx < nz4; idx += NT) {
            cpasync16(smB0 + idx * 16, p0 + idx);
            cpasync16(smB1 + idx * 16, p1 + idx);
        }
        cpcommit(); cpwait0();
    }
    __syncthreads();

    if (isCrit) {
        // =================== CRIT group: warps 0-5 ===================
        for (int t = 0; t < S_LEN; t++) {
            float* X = (t & 1) ? Bf1 : Bf0;            // P(t); becomes z1p

            // ---- act0(t): h0 = lstm0(X + z0s + wpd*pd), (u,u+1) pairs ----
#pragma unroll
            for (int n = 0; n < 4; n++) {
                int idx = tid + n * 192;
                if (idx < nact2) {
                    int b = idx / 25, up = idx - b * 25;
                    const u64* zr = (const u64*)(X + b * 200);
                    const u64* z0 = (const u64*)(z0s + b * 200);
                    const u64* wp = (const u64*)wpd_s;
                    float pdb = pd_s[b];
                    float2 zi = unpack2(zr[up]),      ai = unpack2(z0[up]),      wi = unpack2(wp[up]);
                    float2 zf = unpack2(zr[up + 25]), af = unpack2(z0[up + 25]), wf = unpack2(wp[up + 25]);
                    float2 zg = unpack2(zr[up + 50]), ag = unpack2(z0[up + 50]), wg = unpack2(wp[up + 50]);
                    float2 zo = unpack2(zr[up + 75]), ao = unpack2(z0[up + 75]), wo = unpack2(wp[up + 75]);
                    float ivx = zi.x + ai.x + wi.x * pdb, ivy = zi.y + ai.y + wi.y * pdb;
                    float fvx = zf.x + af.x + wf.x * pdb, fvy = zf.y + af.y + wf.y * pdb;
                    float gvx = zg.x + ag.x + wg.x * pdb, gvy = zg.y + ag.y + wg.y * pdb;
                    float ovx = zo.x + ao.x + wo.x * pdb, ovy = zo.y + ao.y + wo.y * pdb;
                    float cx = sigf(fvx) * c0r[2 * n]     + sigf(ivx) * tanha(gvx);
                    float cy = sigf(fvy) * c0r[2 * n + 1] + sigf(ivy) * tanha(gvy);
                    c0r[2 * n] = cx; c0r[2 * n + 1] = cy;
                    ((u64*)(h0s + b * 52))[up] = pack2(sigf(ovx) * tanha(cx),
                                                       sigf(ovy) * tanha(cy));
                }
            }
            barS(5, 192);          // h0s visible in CRIT; X fully consumed
            barA(3, 384);          // h0-ready -> BG

            // ---- z1p(t) = bias1 + Wih1*h0 -> X ----
            MV1(h0s, wrA, (X + tid), bias0);
            if (wid == 5 && lane >= 24)
                MV1(h0s, wrB, (X + 168 + lane), bias1e);
            barS(1, 384);          // wait BG p2(t); also orders CRIT z1p STS

            // ---- act1(t): h1 = lstm1(z1p + p2) ----
#pragma unroll
            for (int n = 0; n < 4; n++) {
                int idx = tid + n * 192;
                if (idx < nact2) {
                    int b = idx / 25, up = idx - b * 25;
                    const u64* zr = (const u64*)(X + b * 200);
                    const u64* pr = (const u64*)(p2s + b * 200);
                    float2 zi = unpack2(zr[up]),      pi = unpack2(pr[up]);
                    float2 zf = unpack2(zr[up + 25]), pf = unpack2(pr[up + 25]);
                    float2 zg = unpack2(zr[up + 50]), pg = unpack2(pr[up + 50]);
                    float2 zo = unpack2(zr[up + 75]), po = unpack2(pr[up + 75]);
                    float ivx = zi.x + pi.x, ivy = zi.y + pi.y;
                    float fvx = zf.x + pf.x, fvy = zf.y + pf.y;
                    float gvx = zg.x + pg.x, gvy = zg.y + pg.y;
                    float ovx = zo.x + po.x, ovy = zo.y + po.y;
                    float cx = sigf(fvx) * c1r[2 * n]     + sigf(ivx) * tanha(gvx);
                    float cy = sigf(fvy) * c1r[2 * n + 1] + sigf(ivy) * tanha(gvy);
                    c1r[2 * n] = cx; c1r[2 * n + 1] = cy;
                    ((u64*)(h1s + b * 52))[up] = pack2(sigf(ovx) * tanha(cx),
                                                       sigf(ovy) * tanha(cy));
                }
            }
            barS(5, 192);          // h1s visible in CRIT
            barA(2, 384);          // h1-ready -> BG

            // ---- head(t) on warps 0-4; warp5 computes z0s/p2 extras ----
            if (wid < 5) {
                for (int b = wid; b < bt; b += 5) {
                    float v = 0.0f;
                    if (lane < 25) {
                        const u64* hv = (const u64*)(h1s + b * 52);
                        u64 acc0 = 0ull, acc1 = 0ull;
#pragma unroll
                        for (int uu = 0; uu < 12; uu++) {
                            acc0 = ffma2(wrB[2 * uu],     hv[2 * uu],     acc0);
                            acc1 = ffma2(wrB[2 * uu + 1], hv[2 * uu + 1], acc1);
                        }
                        acc0 = ffma2(wrB[24], hv[24], acc0);
                        float2 f0 = unpack2(acc0), f1 = unpack2(acc1);
                        v = w2v * fmaxf(f0.x + f0.y + f1.x + f1.y + b1v, 0.0f);
                    }
#pragma unroll
                    for (int k = 16; k > 0; k >>= 1) v += __shfl_xor_sync(0xFFFFFFFFu, v, k);
                    if (lane == 0) {
                        float nd = pd_s[b] + 0.2f * tanha(v + b2sp[0]);
                        nd = fminf(fmaxf(nd, -1.5f), 1.5f);
                        pd_s[b] = nd;
                        out[(size_t)(b0 + b) * S_LEN + t] = nd;
                    }
                }
            } else if (lane < 16) {
                // extras for next step: z0s rows 192-199 (from h0(t)),
                // p2 rows 192-199 (from h1(t))
                const float* sp = (lane < 8) ? h0s : h1s;
                float* dp = (lane < 8) ? (z0s + 192 + lane) : (p2s + 184 + lane);
                MV1(sp, wrB, dp, 0.0f);
            }
            barS(5, 192);          // pd_s + extras visible in CRIT
            barS(4, 384);          // wait BG z0s(t+1) (also publishes P(t+1))
        }
    } else {
        // =================== BG group: warps 6-11 ===================
        const int g = tid - 192;
        for (int t = 0; t < S_LEN; t++) {
            const uint32_t Xsm = (t & 1) ? smB1 : smB0;   // buffer of P(t)
            cpwait0();             // prefetch issued at t-1 has landed
            // ---- p2(t) = Whh1 * h1(t-1), rows 0-191 ----
            MV1(h1s, wrB, (p2s + g), 0.0f);
            barA(1, 384);          // p2-ready -> CRIT
            barS(3, 384);          // wait h0(t)
            // ---- z0s(t+1) = Whh0 * h0(t), rows 0-191 ----
            MV1(h0s, wrA, (z0s + g), 0.0f);
            barA(4, 384);          // z0s-ready -> CRIT
            barS(2, 384);          // wait h1(t)
            // ---- prefetch P(t+2) into the buffer X(t) just freed ----
            if (t + 2 < S_LEN) {
                const float4* psrc = (const float4*)(g_pre0 + ((size_t)(t + 2) * B_TOT + b0) * 200);
                for (int idx = g; idx < nz4; idx += 192)
                    cpasync16(Xsm + idx * 16, psrc + idx);
            }
            cpcommit();
        }
    }
}

// ---------------------------------------------------------------------------
extern "C" void kernel_launch(void* const* d_in, const int* in_sizes, int n_in,
                              void* d_out, int out_size) {
    const float* features = (const float*)d_in[0];
    const float* w_ih0    = (const float*)d_in[1];
    const float* w_hh0    = (const float*)d_in[2];
    const float* b_ih0    = (const float*)d_in[3];
    const float* b_hh0    = (const float*)d_in[4];
    const float* w_ih1    = (const float*)d_in[5];
    const float* w_hh1    = (const float*)d_in[6];
    const float* b_ih1    = (const float*)d_in[7];
    const float* b_hh1    = (const float*)d_in[8];
    const float* w1       = (const float*)d_in[9];
    const float* b1       = (const float*)d_in[10];
    const float* w2       = (const float*)d_in[11];
    const float* b2       = (const float*)d_in[12];
    float* out = (float*)d_out;

    static bool attr_set = false;
    if (!attr_set) {
        cudaFuncSetAttribute(rec_kernel, cudaFuncAttributeMaxDynamicSharedMemorySize,
                             SM_FLOATS * 4);
        attr_set = true;
    }

    pre0f_kernel<<<B_TOT, 256>>>(features, w_ih0, b_ih0, b_hh0);
    rec_kernel<<<(B_TOT + BT - 1) / BT, NT, SM_FLOATS * 4>>>(
        w_ih0, w_hh0, w_ih1, w_hh1, b_ih1, b_hh1, w1, b1, w2, b2, out);
}